// round 7
// baseline (speedup 1.0000x reference)
#include <cuda_runtime.h>

#define N_NODES 100000
#define N_EDGES 1600000
#define F 64
#define SCAN_BLK 512
#define NB ((N_NODES + SCAN_BLK - 1) / SCAN_BLK)   // 196

// Scratch (device globals — no allocation in kernel_launch)
__device__ int   g_cnt[N_NODES];
__device__ int   g_scan[N_NODES];
__device__ int   g_bsum[NB];
__device__ int   g_rowptr[N_NODES + 1];
__device__ int   g_cursor[N_NODES];
__device__ int   g_srt[N_EDGES];        // src indices bucketed by dst
__device__ float g_dinv[N_NODES];
__device__ float g_xs[N_NODES * F];     // (x @ W) * dinv[row]

__global__ void k_zero_cnt() {
    int i = blockIdx.x * blockDim.x + threadIdx.x;
    if (i < N_NODES) g_cnt[i] = 0;
}

// count in-degree (real edges only); 4 edges/thread via int4
__global__ void k_count(const int* __restrict__ ei) {
    int t = blockIdx.x * blockDim.x + threadIdx.x;
    if (t < N_EDGES / 4) {
        int4 d4 = ((const int4*)(ei + N_EDGES))[t];
        if ((unsigned)d4.x < N_NODES) atomicAdd(&g_cnt[d4.x], 1);
        if ((unsigned)d4.y < N_NODES) atomicAdd(&g_cnt[d4.y], 1);
        if ((unsigned)d4.z < N_NODES) atomicAdd(&g_cnt[d4.z], 1);
        if ((unsigned)d4.w < N_NODES) atomicAdd(&g_cnt[d4.w], 1);
    }
}

// per-block inclusive scan of g_cnt
__global__ void __launch_bounds__(SCAN_BLK) k_scan_block() {
    __shared__ int s[SCAN_BLK];
    int t = threadIdx.x;
    int i = blockIdx.x * SCAN_BLK + t;
    s[t] = (i < N_NODES) ? g_cnt[i] : 0;
    __syncthreads();
    #pragma unroll
    for (int off = 1; off < SCAN_BLK; off <<= 1) {
        int v = (t >= off) ? s[t - off] : 0;
        __syncthreads();
        s[t] += v;
        __syncthreads();
    }
    if (i < N_NODES) g_scan[i] = s[t];
    if (t == SCAN_BLK - 1) g_bsum[blockIdx.x] = s[t];
}

// finalize: each block computes its own cross-block prefix from g_bsum
// (<=196 entries, warp-reduced), then rowptr/cursor/dinv. One block per scan block.
__global__ void __launch_bounds__(SCAN_BLK) k_finalize() {
    __shared__ int base_sh;
    int b = blockIdx.x;
    int t = threadIdx.x;
    if (t < 32) {
        int s = 0;
        for (int j = t; j < b; j += 32) s += g_bsum[j];
        #pragma unroll
        for (int o = 16; o; o >>= 1) s += __shfl_xor_sync(0xffffffffu, s, o);
        if (t == 0) base_sh = s;
    }
    __syncthreads();
    int i = b * SCAN_BLK + t;
    if (i < N_NODES) {
        int incl = g_scan[i] + base_sh;
        int cnt = g_cnt[i];
        int excl = incl - cnt;
        g_rowptr[i] = excl;
        g_cursor[i] = excl;
        if (i == N_NODES - 1) g_rowptr[N_NODES] = incl;
        g_dinv[i] = rsqrtf((float)(cnt + 1));     // +1 self-loop
    }
}

// bucket src indices by dst; 4 edges/thread via int4 on both streams
__global__ void k_fill(const int* __restrict__ ei) {
    int t = blockIdx.x * blockDim.x + threadIdx.x;
    if (t < N_EDGES / 4) {
        int4 s4 = ((const int4*)ei)[t];
        int4 d4 = ((const int4*)(ei + N_EDGES))[t];
        if ((unsigned)s4.x < N_NODES && (unsigned)d4.x < N_NODES)
            g_srt[atomicAdd(&g_cursor[d4.x], 1)] = s4.x;
        if ((unsigned)s4.y < N_NODES && (unsigned)d4.y < N_NODES)
            g_srt[atomicAdd(&g_cursor[d4.y], 1)] = s4.y;
        if ((unsigned)s4.z < N_NODES && (unsigned)d4.z < N_NODES)
            g_srt[atomicAdd(&g_cursor[d4.z], 1)] = s4.z;
        if ((unsigned)s4.w < N_NODES && (unsigned)d4.w < N_NODES)
            g_srt[atomicAdd(&g_cursor[d4.w], 1)] = s4.w;
    }
}

// GEMM: K split into 2 chunks of 32 so W-column regs drop 64 -> 32 (occupancy).
#define ROWS_BLK 32
__global__ void __launch_bounds__(256) k_gemm(const float* __restrict__ x,
                                              const float* __restrict__ W) {
    __shared__ float4 xsh[ROWS_BLK * 16];
    int tid = threadIdx.x;
    int c  = tid & 63;
    int rg = tid >> 6;

    int row0 = blockIdx.x * ROWS_BLK;
    const float4* x4 = (const float4*)(x + row0 * F);
    #pragma unroll
    for (int i = tid; i < ROWS_BLK * 16; i += 256) xsh[i] = x4[i];
    __syncthreads();

    float acc[8];
    #pragma unroll
    for (int rr = 0; rr < 8; rr++) acc[rr] = 0.0f;

    #pragma unroll 1
    for (int h = 0; h < 2; h++) {
        float Wc[32];
        #pragma unroll
        for (int k = 0; k < 32; k++) Wc[k] = W[(h * 32 + k) * F + c];
        #pragma unroll
        for (int rr = 0; rr < 8; rr++) {
            int r = rg * 8 + rr;
            float a = 0.0f;
            #pragma unroll
            for (int k0 = 0; k0 < 8; k0++) {
                float4 xv = xsh[r * 16 + h * 8 + k0];   // broadcast within warp
                a += xv.x * Wc[4 * k0 + 0];
                a += xv.y * Wc[4 * k0 + 1];
                a += xv.z * Wc[4 * k0 + 2];
                a += xv.w * Wc[4 * k0 + 3];
            }
            acc[rr] += a;
        }
    }

    #pragma unroll
    for (int rr = 0; rr < 8; rr++) {
        int row = row0 + rg * 8 + rr;
        g_xs[row * F + c] = acc[rr] * g_dinv[row];
    }
}

// One warp per dst node: register accumulation of in-edge messages,
// fused self-loop + dinv[dst] + bias + PReLU. No atomics on out.
__global__ void __launch_bounds__(256) k_accum(float* __restrict__ out,
                                               const float* __restrict__ b,
                                               const float* __restrict__ a) {
    int w = (blockIdx.x * blockDim.x + threadIdx.x) >> 5;
    int lane = threadIdx.x & 31;
    if (w >= N_NODES) return;
    int d = w;
    int beg = g_rowptr[d];
    int end = g_rowptr[d + 1];

    const float2* xs2 = (const float2*)g_xs;
    int lp = lane;
    float2 acc0 = xs2[d * 32 + lp];            // self-loop term (xs[d])
    float2 acc1 = make_float2(0.0f, 0.0f);

    int i = beg;
    while (i < end) {
        int m = end - i;
        if (m > 32) m = 32;
        int my = (lane < m) ? __ldg(g_srt + i + lane) : 0;
        for (int j = 0; j < m; j++) {
            int s = __shfl_sync(0xffffffffu, my, j);
            float2 v = xs2[s * 32 + lp];
            if (j & 1) { acc1.x += v.x; acc1.y += v.y; }
            else       { acc0.x += v.x; acc0.y += v.y; }
        }
        i += m;
    }

    float di = g_dinv[d];
    float2 bb = ((const float2*)b)[lp];
    float slope = a[0];
    float ox = (acc0.x + acc1.x) * di + bb.x;
    float oy = (acc0.y + acc1.y) * di + bb.y;
    ox = (ox >= 0.0f) ? ox : slope * ox;
    oy = (oy >= 0.0f) ? oy : slope * oy;
    ((float2*)out)[d * 32 + lp] = make_float2(ox, oy);
}

extern "C" void kernel_launch(void* const* d_in, const int* in_sizes, int n_in,
                              void* d_out, int out_size) {
    const float* x  = (const float*)d_in[0];
    const int*   ei = (const int*)d_in[1];   // edge_index [2, E] (int32)
    const float* W  = (const float*)d_in[2];
    const float* b  = (const float*)d_in[3];
    const float* a  = (const float*)d_in[4];
    float* out = (float*)d_out;

    k_zero_cnt<<<(N_NODES + 255) / 256, 256>>>();
    k_count<<<(N_EDGES / 4 + 255) / 256, 256>>>(ei);
    k_scan_block<<<NB, SCAN_BLK>>>();
    k_finalize<<<NB, SCAN_BLK>>>();
    k_fill<<<(N_EDGES / 4 + 255) / 256, 256>>>(ei);
    k_gemm<<<N_NODES / ROWS_BLK, 256>>>(x, W);
    k_accum<<<(N_NODES * 32 + 255) / 256, 256>>>(out, b, a);
}

// round 8
// speedup vs baseline: 1.0338x; 1.0338x over previous
#include <cuda_runtime.h>

#define N_NODES 100000
#define N_EDGES 1600000
#define F 64
#define SCAN_BLK 512
#define NB ((N_NODES + SCAN_BLK - 1) / SCAN_BLK)   // 196

// Scratch (device globals — zero-initialized at load; no allocation in kernel_launch)
__device__ int   g_cnt[N_NODES];        // zeroed by k_finalize after each use
__device__ int   g_scan[N_NODES];
__device__ int   g_bsum[NB];
__device__ int   g_rowptr[N_NODES + 1];
__device__ int   g_cursor[N_NODES];
__device__ int   g_srt[N_EDGES];        // src indices bucketed by dst
__device__ float g_dinv[N_NODES];
__device__ float g_xw[N_NODES * F];     // x @ W (unscaled)

// count in-degree (real edges only); 4 edges/thread via int4
__global__ void k_count(const int* __restrict__ ei) {
    int t = blockIdx.x * blockDim.x + threadIdx.x;
    if (t < N_EDGES / 4) {
        int4 d4 = ((const int4*)(ei + N_EDGES))[t];
        if ((unsigned)d4.x < N_NODES) atomicAdd(&g_cnt[d4.x], 1);
        if ((unsigned)d4.y < N_NODES) atomicAdd(&g_cnt[d4.y], 1);
        if ((unsigned)d4.z < N_NODES) atomicAdd(&g_cnt[d4.z], 1);
        if ((unsigned)d4.w < N_NODES) atomicAdd(&g_cnt[d4.w], 1);
    }
}

// per-block inclusive scan of g_cnt
__global__ void __launch_bounds__(SCAN_BLK) k_scan_block() {
    __shared__ int s[SCAN_BLK];
    int t = threadIdx.x;
    int i = blockIdx.x * SCAN_BLK + t;
    s[t] = (i < N_NODES) ? g_cnt[i] : 0;
    __syncthreads();
    #pragma unroll
    for (int off = 1; off < SCAN_BLK; off <<= 1) {
        int v = (t >= off) ? s[t - off] : 0;
        __syncthreads();
        s[t] += v;
        __syncthreads();
    }
    if (i < N_NODES) g_scan[i] = s[t];
    if (t == SCAN_BLK - 1) g_bsum[blockIdx.x] = s[t];
}

// finalize: per-block cross-block prefix from g_bsum (warp-reduced),
// then rowptr/cursor/dinv; resets g_cnt for the next graph replay.
__global__ void __launch_bounds__(SCAN_BLK) k_finalize() {
    __shared__ int base_sh;
    int b = blockIdx.x;
    int t = threadIdx.x;
    if (t < 32) {
        int s = 0;
        for (int j = t; j < b; j += 32) s += g_bsum[j];
        #pragma unroll
        for (int o = 16; o; o >>= 1) s += __shfl_xor_sync(0xffffffffu, s, o);
        if (t == 0) base_sh = s;
    }
    __syncthreads();
    int i = b * SCAN_BLK + t;
    if (i < N_NODES) {
        int incl = g_scan[i] + base_sh;
        int cnt = g_cnt[i];
        g_cnt[i] = 0;                              // restore invariant for replay
        int excl = incl - cnt;
        g_rowptr[i] = excl;
        g_cursor[i] = excl;
        if (i == N_NODES - 1) g_rowptr[N_NODES] = incl;
        g_dinv[i] = rsqrtf((float)(cnt + 1));      // +1 self-loop
    }
}

// bucket src indices by dst; 4 edges/thread via int4 on both streams
__global__ void k_fill(const int* __restrict__ ei) {
    int t = blockIdx.x * blockDim.x + threadIdx.x;
    if (t < N_EDGES / 4) {
        int4 s4 = ((const int4*)ei)[t];
        int4 d4 = ((const int4*)(ei + N_EDGES))[t];
        if ((unsigned)s4.x < N_NODES && (unsigned)d4.x < N_NODES)
            g_srt[atomicAdd(&g_cursor[d4.x], 1)] = s4.x;
        if ((unsigned)s4.y < N_NODES && (unsigned)d4.y < N_NODES)
            g_srt[atomicAdd(&g_cursor[d4.y], 1)] = s4.y;
        if ((unsigned)s4.z < N_NODES && (unsigned)d4.z < N_NODES)
            g_srt[atomicAdd(&g_cursor[d4.z], 1)] = s4.z;
        if ((unsigned)s4.w < N_NODES && (unsigned)d4.w < N_NODES)
            g_srt[atomicAdd(&g_cursor[d4.w], 1)] = s4.w;
    }
}

// GEMM (R5 form, no dinv dependency): W column in registers, x via broadcast LDS.128.
#define ROWS_BLK 32
__global__ void __launch_bounds__(256) k_gemm(const float* __restrict__ x,
                                              const float* __restrict__ W) {
    __shared__ float4 xsh[ROWS_BLK * 16];
    int tid = threadIdx.x;
    int c  = tid & 63;
    int rg = tid >> 6;

    float Wc[F];
    #pragma unroll
    for (int k = 0; k < F; k++) Wc[k] = W[k * F + c];

    int row0 = blockIdx.x * ROWS_BLK;
    const float4* x4 = (const float4*)(x + row0 * F);
    #pragma unroll
    for (int i = tid; i < ROWS_BLK * 16; i += 256) xsh[i] = x4[i];
    __syncthreads();

    #pragma unroll
    for (int rr = 0; rr < 8; rr++) {
        int r = rg * 8 + rr;
        float acc = 0.0f;
        #pragma unroll
        for (int k0 = 0; k0 < 16; k0++) {
            float4 xv = xsh[r * 16 + k0];
            acc += xv.x * Wc[4 * k0 + 0];
            acc += xv.y * Wc[4 * k0 + 1];
            acc += xv.z * Wc[4 * k0 + 2];
            acc += xv.w * Wc[4 * k0 + 3];
        }
        g_xw[(row0 + r) * F + c] = acc;
    }
}

// One warp per dst node: gather xw[s]*dinv[s], add self, scale by dinv[d],
// fused bias + PReLU. No atomics.
__global__ void __launch_bounds__(256) k_accum(float* __restrict__ out,
                                               const float* __restrict__ b,
                                               const float* __restrict__ a) {
    int d = (blockIdx.x * blockDim.x + threadIdx.x) >> 5;
    int lane = threadIdx.x & 31;
    if (d >= N_NODES) return;
    int beg = g_rowptr[d];
    int end = g_rowptr[d + 1];
    float dd = g_dinv[d];

    const float2* xw2 = (const float2*)g_xw;
    int lp = lane;
    float2 self = xw2[d * 32 + lp];
    float2 acc0 = make_float2(self.x * dd, self.y * dd);   // xw[d]*dinv[d]
    float2 acc1 = make_float2(0.0f, 0.0f);

    int i = beg;
    while (i < end) {
        int m = end - i;
        if (m > 32) m = 32;
        int   my = 0;
        float mw = 0.0f;
        if (lane < m) {
            my = __ldg(g_srt + i + lane);
            mw = __ldg(g_dinv + my);
        }
        for (int j = 0; j < m; j++) {
            int   s  = __shfl_sync(0xffffffffu, my, j);
            float ws = __shfl_sync(0xffffffffu, mw, j);
            float2 v = xw2[s * 32 + lp];
            if (j & 1) { acc1.x += v.x * ws; acc1.y += v.y * ws; }
            else       { acc0.x += v.x * ws; acc0.y += v.y * ws; }
        }
        i += m;
    }

    float2 bb = ((const float2*)b)[lp];
    float slope = a[0];
    float ox = (acc0.x + acc1.x) * dd + bb.x;
    float oy = (acc0.y + acc1.y) * dd + bb.y;
    ox = (ox >= 0.0f) ? ox : slope * ox;
    oy = (oy >= 0.0f) ? oy : slope * oy;
    ((float2*)out)[d * 32 + lp] = make_float2(ox, oy);
}

extern "C" void kernel_launch(void* const* d_in, const int* in_sizes, int n_in,
                              void* d_out, int out_size) {
    const float* x  = (const float*)d_in[0];
    const int*   ei = (const int*)d_in[1];   // edge_index [2, E] (int32)
    const float* W  = (const float*)d_in[2];
    const float* b  = (const float*)d_in[3];
    const float* a  = (const float*)d_in[4];
    float* out = (float*)d_out;

    static cudaStream_t s1 = nullptr;
    static cudaEvent_t  e0 = nullptr, e1 = nullptr;
    if (!s1) {
        cudaStreamCreateWithFlags(&s1, cudaStreamNonBlocking);
        cudaEventCreateWithFlags(&e0, cudaEventDisableTiming);
        cudaEventCreateWithFlags(&e1, cudaEventDisableTiming);
    }

    // Fork: GEMM on s1, CSR build on the launch stream.
    cudaEventRecord(e0, 0);
    cudaStreamWaitEvent(s1, e0, 0);
    k_gemm<<<N_NODES / ROWS_BLK, 256, 0, s1>>>(x, W);

    k_count<<<(N_EDGES / 4 + 255) / 256, 256>>>(ei);
    k_scan_block<<<NB, SCAN_BLK>>>();
    k_finalize<<<NB, SCAN_BLK>>>();
    k_fill<<<(N_EDGES / 4 + 255) / 256, 256>>>(ei);

    // Join, then accumulate.
    cudaEventRecord(e1, s1);
    cudaStreamWaitEvent(0, e1, 0);
    k_accum<<<(N_NODES * 32 + 255) / 256, 256>>>(out, b, a);
}

// round 9
// speedup vs baseline: 1.0525x; 1.0180x over previous
#include <cuda_runtime.h>
#include <cuda_fp16.h>

#define N_NODES 100000
#define N_EDGES 1600000
#define F 64
#define SCAN_BLK 512
#define NB ((N_NODES + SCAN_BLK - 1) / SCAN_BLK)   // 196

// Scratch (device globals — zero-initialized at load; no allocation in kernel_launch)
__device__ int    g_cnt[N_NODES];        // zeroed by k_finalize after each use
__device__ int    g_scan[N_NODES];
__device__ int    g_bsum[NB];
__device__ int    g_rowptr[N_NODES + 1];
__device__ int    g_cursor[N_NODES];
__device__ int    g_srt[N_EDGES];        // src indices bucketed by dst
__device__ float  g_dinv[N_NODES];
__device__ __half g_xwh[N_NODES * F];    // x @ W, fp16 (12.8 MB — halves gather traffic)

// count in-degree (real edges only); 4 edges/thread via int4
__global__ void k_count(const int* __restrict__ ei) {
    int t = blockIdx.x * blockDim.x + threadIdx.x;
    if (t < N_EDGES / 4) {
        int4 d4 = ((const int4*)(ei + N_EDGES))[t];
        if ((unsigned)d4.x < N_NODES) atomicAdd(&g_cnt[d4.x], 1);
        if ((unsigned)d4.y < N_NODES) atomicAdd(&g_cnt[d4.y], 1);
        if ((unsigned)d4.z < N_NODES) atomicAdd(&g_cnt[d4.z], 1);
        if ((unsigned)d4.w < N_NODES) atomicAdd(&g_cnt[d4.w], 1);
    }
}

// per-block inclusive scan of g_cnt
__global__ void __launch_bounds__(SCAN_BLK) k_scan_block() {
    __shared__ int s[SCAN_BLK];
    int t = threadIdx.x;
    int i = blockIdx.x * SCAN_BLK + t;
    s[t] = (i < N_NODES) ? g_cnt[i] : 0;
    __syncthreads();
    #pragma unroll
    for (int off = 1; off < SCAN_BLK; off <<= 1) {
        int v = (t >= off) ? s[t - off] : 0;
        __syncthreads();
        s[t] += v;
        __syncthreads();
    }
    if (i < N_NODES) g_scan[i] = s[t];
    if (t == SCAN_BLK - 1) g_bsum[blockIdx.x] = s[t];
}

// finalize: per-block cross-block prefix from g_bsum (warp-reduced),
// then rowptr/cursor/dinv; resets g_cnt for the next graph replay.
__global__ void __launch_bounds__(SCAN_BLK) k_finalize() {
    __shared__ int base_sh;
    int b = blockIdx.x;
    int t = threadIdx.x;
    if (t < 32) {
        int s = 0;
        for (int j = t; j < b; j += 32) s += g_bsum[j];
        #pragma unroll
        for (int o = 16; o; o >>= 1) s += __shfl_xor_sync(0xffffffffu, s, o);
        if (t == 0) base_sh = s;
    }
    __syncthreads();
    int i = b * SCAN_BLK + t;
    if (i < N_NODES) {
        int incl = g_scan[i] + base_sh;
        int cnt = g_cnt[i];
        g_cnt[i] = 0;                              // restore invariant for replay
        int excl = incl - cnt;
        g_rowptr[i] = excl;
        g_cursor[i] = excl;
        if (i == N_NODES - 1) g_rowptr[N_NODES] = incl;
        g_dinv[i] = rsqrtf((float)(cnt + 1));      // +1 self-loop
    }
}

// bucket src indices by dst; 4 edges/thread via int4 on both streams
__global__ void k_fill(const int* __restrict__ ei) {
    int t = blockIdx.x * blockDim.x + threadIdx.x;
    if (t < N_EDGES / 4) {
        int4 s4 = ((const int4*)ei)[t];
        int4 d4 = ((const int4*)(ei + N_EDGES))[t];
        if ((unsigned)s4.x < N_NODES && (unsigned)d4.x < N_NODES)
            g_srt[atomicAdd(&g_cursor[d4.x], 1)] = s4.x;
        if ((unsigned)s4.y < N_NODES && (unsigned)d4.y < N_NODES)
            g_srt[atomicAdd(&g_cursor[d4.y], 1)] = s4.y;
        if ((unsigned)s4.z < N_NODES && (unsigned)d4.z < N_NODES)
            g_srt[atomicAdd(&g_cursor[d4.z], 1)] = s4.z;
        if ((unsigned)s4.w < N_NODES && (unsigned)d4.w < N_NODES)
            g_srt[atomicAdd(&g_cursor[d4.w], 1)] = s4.w;
    }
}

// GEMM: fp32 compute (W column in registers, x via broadcast LDS.128), fp16 store.
#define ROWS_BLK 32
__global__ void __launch_bounds__(256) k_gemm(const float* __restrict__ x,
                                              const float* __restrict__ W) {
    __shared__ float4 xsh[ROWS_BLK * 16];
    int tid = threadIdx.x;
    int c  = tid & 63;
    int rg = tid >> 6;

    float Wc[F];
    #pragma unroll
    for (int k = 0; k < F; k++) Wc[k] = W[k * F + c];

    int row0 = blockIdx.x * ROWS_BLK;
    const float4* x4 = (const float4*)(x + row0 * F);
    #pragma unroll
    for (int i = tid; i < ROWS_BLK * 16; i += 256) xsh[i] = x4[i];
    __syncthreads();

    #pragma unroll
    for (int rr = 0; rr < 8; rr++) {
        int r = rg * 8 + rr;
        float acc = 0.0f;
        #pragma unroll
        for (int k0 = 0; k0 < 16; k0++) {
            float4 xv = xsh[r * 16 + k0];
            acc += xv.x * Wc[4 * k0 + 0];
            acc += xv.y * Wc[4 * k0 + 1];
            acc += xv.z * Wc[4 * k0 + 2];
            acc += xv.w * Wc[4 * k0 + 3];
        }
        g_xwh[(row0 + r) * F + c] = __float2half_rn(acc);
    }
}

// One warp per dst node: gather xwh[s] (half2) * dinv[s], fp32 accumulate,
// add self, scale by dinv[d], fused bias + PReLU. No atomics.
__global__ void __launch_bounds__(256) k_accum(float* __restrict__ out,
                                               const float* __restrict__ b,
                                               const float* __restrict__ a) {
    int d = (blockIdx.x * blockDim.x + threadIdx.x) >> 5;
    int lane = threadIdx.x & 31;
    if (d >= N_NODES) return;
    int beg = g_rowptr[d];
    int end = g_rowptr[d + 1];
    float dd = g_dinv[d];

    const __half2* xw2 = (const __half2*)g_xwh;
    int lp = lane;                                  // half2 slot (cols 2lp, 2lp+1)
    float2 self = __half22float2(xw2[d * 32 + lp]);
    float2 acc0 = make_float2(self.x * dd, self.y * dd);   // xw[d]*dinv[d]
    float2 acc1 = make_float2(0.0f, 0.0f);

    int i = beg;
    while (i < end) {
        int m = end - i;
        if (m > 32) m = 32;
        int   my = 0;
        float mw = 0.0f;
        if (lane < m) {
            my = __ldg(g_srt + i + lane);
            mw = __ldg(g_dinv + my);
        }
        for (int j = 0; j < m; j++) {
            int   s  = __shfl_sync(0xffffffffu, my, j);
            float ws = __shfl_sync(0xffffffffu, mw, j);
            float2 v = __half22float2(xw2[s * 32 + lp]);
            if (j & 1) { acc1.x += v.x * ws; acc1.y += v.y * ws; }
            else       { acc0.x += v.x * ws; acc0.y += v.y * ws; }
        }
        i += m;
    }

    float2 bb = ((const float2*)b)[lp];
    float slope = a[0];
    float ox = (acc0.x + acc1.x) * dd + bb.x;
    float oy = (acc0.y + acc1.y) * dd + bb.y;
    ox = (ox >= 0.0f) ? ox : slope * ox;
    oy = (oy >= 0.0f) ? oy : slope * oy;
    ((float2*)out)[d * 32 + lp] = make_float2(ox, oy);
}

extern "C" void kernel_launch(void* const* d_in, const int* in_sizes, int n_in,
                              void* d_out, int out_size) {
    const float* x  = (const float*)d_in[0];
    const int*   ei = (const int*)d_in[1];   // edge_index [2, E] (int32)
    const float* W  = (const float*)d_in[2];
    const float* b  = (const float*)d_in[3];
    const float* a  = (const float*)d_in[4];
    float* out = (float*)d_out;

    k_count<<<(N_EDGES / 4 + 255) / 256, 256>>>(ei);
    k_scan_block<<<NB, SCAN_BLK>>>();
    k_finalize<<<NB, SCAN_BLK>>>();
    k_gemm<<<N_NODES / ROWS_BLK, 256>>>(x, W);
    k_fill<<<(N_EDGES / 4 + 255) / 256, 256>>>(ei);
    k_accum<<<(N_NODES * 32 + 255) / 256, 256>>>(out, b, a);
}